// round 17
// baseline (speedup 1.0000x reference)
#include <cuda_runtime.h>
#include <math.h>
#include <float.h>

// ---------------- problem constants ----------------
// x: (B=16, C=1024, H=64, W=64) fp32. out: (16,1024,1,1) fp32.
// 14 distinct regions (full region weighted x2):
//  r0:  (0,0,64)
//  r1..r4:  wl=42 at (i,j) in {0,22}x{0,22}  (i-major)
//  r5..r13: wl=32 at (i,j) in {0,16,32}^2    (i-major)
#define B 16
#define C 1024
#define HW 64
#define NPIX 4096          // 64*64
#define NREG 14
#define NTILE 1024         // work tiles: (b 0..15) x (g 0..63), 16 channels each
#define NBLK 296           // persistent blocks (2 per SM x 148)
#define FXSCALE 16777216.0f   // 2^24 fixed-point scale for channel sums

// Elementary segments (rows and cols use the same decomposition):
// E0[0,16) E1[16,22) E2[22,32) E3[32,42) E4[42,48) E5[48,64)
// In "pair" units (2 rows/cols): E0[0,8) E1[8,11) E2[11,16) E3[16,21) E4[21,24) E5[24,32)
__constant__ int c_elemStart[7] = {0, 8, 11, 16, 21, 24, 32};

// Row segment -> up to 2 warp-part codes (code = warp*2 + part), -1 = none.
// Warp w owns rowpairs [4w, 4w+4). Only w2 (boundary pair 11) and w5 (pair 21)
// straddle a segment: w2 partA=pairs{8,9,10} partB={11}; w5 partA={20} partB={21,22,23}.
__constant__ int c_rsPart[6][2] = {
    {0, 2},    // R0 rows[0,16)  = w0 all, w1 all
    {4, -1},   // R1 rows[16,22) = w2 partA
    {5, 6},    // R2 rows[22,32) = w2 partB, w3 all
    {8, 10},   // R3 rows[32,42) = w4 all,  w5 partA
    {11, -1},  // R4 rows[42,48) = w5 partB
    {12, 14}   // R5 rows[48,64) = w6 all,  w7 all
};

// Interval -> elementary bitmask:
// [0,64)=63  [0,42)=15  [22,64)=60  [0,32)=7  [16,48)=30  [32,64)=56
__constant__ int c_rowmask[NREG] = {63, 15,15,60,60, 7,7,7, 30,30,30, 56,56,56};
__constant__ int c_colmask[NREG] = {63, 15,60,15,60, 7,30,56, 7,30,56, 7,30,56};
__constant__ float c_area[NREG] = {4096.f, 1764.f,1764.f,1764.f,1764.f,
                                   1024.f,1024.f,1024.f,1024.f,1024.f,1024.f,1024.f,1024.f,1024.f};

// ---------------- device scratch (no allocations allowed) ----------------
__device__ unsigned long long g_s_fx[B * NPIX];  // fixed-point channel sums (2^24)
__device__ unsigned long long g_tot;             // total of all s_fx (for mean)
__device__ unsigned int g_work;                  // work-steal counter
__device__ float g_vt[NREG * B * C];             // region maxes
__device__ float g_scale[NREG * B];              // per (region,batch) final scale
__device__ int   g_cnt[NREG];                    // tt counts per region

// ================= kernel Z: zero accumulators =================
__global__ __launch_bounds__(256) void kZ() {
    const int i = blockIdx.x * 256 + threadIdx.x;
    g_s_fx[i] = 0ull;
    if (i == 0) { g_tot = 0ull; g_work = 0u; }
    if (i < NREG) g_cnt[i] = 0;
}

// ================= kernel A: persistent CTAs + work stealing =================
// 296 persistent blocks (2/SM) x 256 threads (8 warps) steal 16-channel tiles
// (1024 tiles) via an atomic counter -> near-zero wave-quantization tail.
// Deterministic: tiles write exclusive g_vt slots; all shared accumulation is
// exact integer atomics (order-independent).
// Within a tile: warp w owns pixel rows [8w, 8w+8) (coalesced 512B warp-LDGs);
// the 16-channel loop is barrier-free (warp shuffles + private smem slices).
__global__ __launch_bounds__(256, 2) void kA(const float* __restrict__ x) {
    const int tid = threadIdx.x;
    const int w = tid >> 5;            // warp 0..7 -> rows [8w, 8w+8)
    const int l = tid & 31;            // lane
    const int m = l & 15;              // col-quad: cols [4m, 4m+3]

    __shared__ float smP[16][8][2][32];       // 32 KB, reused per tile
    __shared__ float elemG[16][6][6];         // elementary 6x6 grid per channel
    __shared__ unsigned int s_tile;
    __shared__ long long wtot[8];

    long long tot_acc = 0;             // per-thread exact total across tiles

    while (true) {
        if (tid == 0) s_tile = atomicAdd(&g_work, 1u);
        __syncthreads();               // S0: broadcast tile; also fences prior
                                       // phase-2 reads before smP/elemG reuse
        const unsigned t = s_tile;
        if (t >= NTILE) break;
        const int b = t >> 6;          // batch
        const int g = t & 63;          // channel group (16 channels)

        // per-pixel partial sums over this tile's 16 channels
        float4 sum0 = make_float4(0.f,0.f,0.f,0.f), sum1 = sum0, sum2 = sum0, sum3 = sum0;

        const float4* __restrict__ xbase = reinterpret_cast<const float4*>(
            x + (((size_t)b * C + (size_t)g * 16) * NPIX)) + w * 128 + l;

#pragma unroll
        for (int ch = 0; ch < 16; ch++) {
            const float4* __restrict__ xr = xbase + (size_t)ch * (NPIX / 4);
            float4 v0 = __ldcs(xr);
            float4 v1 = __ldcs(xr + 32);
            float4 v2 = __ldcs(xr + 64);
            float4 v3 = __ldcs(xr + 96);

            sum0.x += v0.x; sum0.y += v0.y; sum0.z += v0.z; sum0.w += v0.w;
            sum1.x += v1.x; sum1.y += v1.y; sum1.z += v1.z; sum1.w += v1.w;
            sum2.x += v2.x; sum2.y += v2.y; sum2.z += v2.z; sum2.w += v2.w;
            sum3.x += v3.x; sum3.y += v3.y; sum3.z += v3.z; sum3.w += v3.w;

            // colpair maxes; iteration i covers rowpair 4w+i (row parity = l>=16)
            float mx[4][2];
            mx[0][0] = fmaxf(v0.x, v0.y); mx[0][1] = fmaxf(v0.z, v0.w);
            mx[1][0] = fmaxf(v1.x, v1.y); mx[1][1] = fmaxf(v1.z, v1.w);
            mx[2][0] = fmaxf(v2.x, v2.y); mx[2][1] = fmaxf(v2.z, v2.w);
            mx[3][0] = fmaxf(v3.x, v3.y); mx[3][1] = fmaxf(v3.z, v3.w);

            // merge the two row parities (rows 2i/2i+1 always share a row segment)
#pragma unroll
            for (int i = 0; i < 4; i++) {
                mx[i][0] = fmaxf(mx[i][0], __shfl_xor_sync(0xffffffffu, mx[i][0], 16));
                mx[i][1] = fmaxf(mx[i][1], __shfl_xor_sync(0xffffffffu, mx[i][1], 16));
            }

            // reduce 4 rowpairs -> <=2 row-parts (uniform branch on warp id)
            float pA[2], pB[2];
#pragma unroll
            for (int p = 0; p < 2; p++) {
                if (w == 2) {          // rowpairs 8,9,10 | 11   (boundary row 22)
                    pA[p] = fmaxf(fmaxf(mx[0][p], mx[1][p]), mx[2][p]);
                    pB[p] = mx[3][p];
                } else if (w == 5) {   // rowpair 20 | 21,22,23  (boundary row 42)
                    pA[p] = mx[0][p];
                    pB[p] = fmaxf(fmaxf(mx[1][p], mx[2][p]), mx[3][p]);
                } else {
                    pA[p] = fmaxf(fmaxf(mx[0][p], mx[1][p]), fmaxf(mx[2][p], mx[3][p]));
                    pB[p] = -INFINITY;
                }
            }

            // lanes 0..15 publish (colpairs 2m, 2m+1) as one float2 each
            if (l < 16) {
                *reinterpret_cast<float2*>(&smP[ch][w][0][2 * m]) = make_float2(pA[0], pA[1]);
                *reinterpret_cast<float2*>(&smP[ch][w][1][2 * m]) = make_float2(pB[0], pB[1]);
            }
        }

        // ---- flush this tile's pixel sums: exact fixed-point atomics ----
        {
            const float* s0 = &sum0.x;
            const float* s1 = &sum1.x;
            const float* s2 = &sum2.x;
            const float* s3 = &sum3.x;
            const int pixbase = b * NPIX;
#pragma unroll
            for (int i = 0; i < 4; i++) {
                const int f4idx = w * 128 + 32 * i + l;
                const float* ss = (i == 0) ? s0 : (i == 1) ? s1 : (i == 2) ? s2 : s3;
#pragma unroll
                for (int c4 = 0; c4 < 4; c4++) {
                    const long long v = llrintf(ss[c4] * FXSCALE);
                    tot_acc += v;
                    atomicAdd(&g_s_fx[pixbase + f4idx * 4 + c4], (unsigned long long)v);
                }
            }
        }

        __syncthreads();   // S1: smP complete

        // phase 2a: 576 jobs = 16 channels x 36 elementary cells
        for (int j = tid; j < 16 * 36; j += 256) {
            const int ch = j / 36;
            const int rc = j % 36;
            const int re = rc / 6, ce = rc % 6;
            const int c0 = c_elemStart[ce], c1 = c_elemStart[ce + 1];
            float mm = -INFINITY;
            const int p0 = c_rsPart[re][0];
            const float* s0 = &smP[ch][p0 >> 1][p0 & 1][0];
            for (int cp = c0; cp < c1; cp++) mm = fmaxf(mm, s0[cp]);
            const int p1 = c_rsPart[re][1];
            if (p1 >= 0) {
                const float* s1 = &smP[ch][p1 >> 1][p1 & 1][0];
                for (int cp = c0; cp < c1; cp++) mm = fmaxf(mm, s1[cp]);
            }
            elemG[ch][re][ce] = mm;
        }
        __syncthreads();   // S2: elemG complete; also fences smP before next tile

        // phase 2b: 224 jobs = 16 channels x 14 regions -> region maxes
        if (tid < 16 * NREG) {
            const int ch = tid / NREG;
            const int r  = tid % NREG;
            const int rm = c_rowmask[r], cm = c_colmask[r];
            float mm = -INFINITY;
#pragma unroll
            for (int re = 0; re < 6; re++) {
                if (!(rm & (1 << re))) continue;
#pragma unroll
                for (int ce = 0; ce < 6; ce++) {
                    if (!(cm & (1 << ce))) continue;
                    mm = fmaxf(mm, elemG[ch][re][ce]);
                }
            }
            g_vt[(r * B + b) * C + g * 16 + ch] = mm;
        }
        // next iteration's S0 fences elemG reads before reuse
    }

    // ---- block total -> one exact integer atomic ----
#pragma unroll
    for (int o = 16; o > 0; o >>= 1)
        tot_acc += __shfl_xor_sync(0xffffffffu, tot_acc, o);
    if (l == 0) wtot[w] = tot_acc;
    __syncthreads();
    if (tid == 0) {
        long long tt2 = 0;
#pragma unroll
        for (int i = 0; i < 8; i++) tt2 += wtot[i];
        atomicAdd(&g_tot, (unsigned long long)tt2);
    }
}

// ================= kernel B2: tt counts via exact integer threshold =================
// tt = (s - mean) > 0  <=>  NPIXTOT * s_fx > tot_fx   (exact in int64)
__global__ __launch_bounds__(1024) void kB2() {
    const int tid = threadIdx.x;
    const int gp = blockIdx.x * 1024 + tid;   // global pixel over (b, p)
    const long long sfx = (long long)g_s_fx[gp];
    const long long tot = (long long)g_tot;
    const bool tt = (sfx * (long long)(B * NPIX)) > tot;

    const int p = gp & (NPIX - 1);
    const int h = p >> 6;
    const int w = p & 63;

    const bool h42a = h < 42, h42b = h >= 22, w42a = w < 42, w42b = w >= 22;
    const bool h32a = h < 32, h32b = (h >= 16 && h < 48), h32c = h >= 32;
    const bool w32a = w < 32, w32b = (w >= 16 && w < 48), w32c = w >= 32;

    bool mem[NREG];
    mem[0]  = true;
    mem[1]  = h42a && w42a;  mem[2]  = h42a && w42b;
    mem[3]  = h42b && w42a;  mem[4]  = h42b && w42b;
    mem[5]  = h32a && w32a;  mem[6]  = h32a && w32b;  mem[7]  = h32a && w32c;
    mem[8]  = h32b && w32a;  mem[9]  = h32b && w32b;  mem[10] = h32b && w32c;
    mem[11] = h32c && w32a;  mem[12] = h32c && w32b;  mem[13] = h32c && w32c;

    unsigned bal[NREG];
#pragma unroll
    for (int r = 0; r < NREG; r++)
        bal[r] = __ballot_sync(0xffffffffu, tt && mem[r]);
    const int lane = tid & 31;
    if (lane < NREG) atomicAdd(&g_cnt[lane], __popc(bal[lane]));  // int atomics: deterministic
}

// ================= kernel C1: per (region,batch) norm -> scale =================
__global__ __launch_bounds__(128) void kC1() {
    const int rb = blockIdx.x;       // rb = r * B + b
    const int r = rb / B;
    const int tid = threadIdx.x;
    const int lane = tid & 31;
    const int warp = tid >> 5;

    const float* vt = &g_vt[rb * C];
    float ss = 0.f;
#pragma unroll
    for (int i = 0; i < 8; i++) {
        float v = vt[tid + i * 128];
        ss += v * v;
    }
#pragma unroll
    for (int o = 16; o > 0; o >>= 1)
        ss += __shfl_xor_sync(0xffffffffu, ss, o);

    __shared__ float wsum[4];
    if (lane == 0) wsum[warp] = ss;
    __syncthreads();
    if (tid == 0) {
        const float nrm = sqrtf(wsum[0] + wsum[1] + wsum[2] + wsum[3]);
        float wgt = (float)g_cnt[r] / c_area[r];
        if (wgt <= (1.0f / 3.0f)) wgt = 0.f;
        if (r == 0) wgt *= 2.0f;            // full region appears twice
        g_scale[rb] = wgt / (nrm + 1e-6f);
    }
}

// ================= kernel C2: final combine =================
__global__ __launch_bounds__(256) void kC2(float* __restrict__ out) {
    const int b = blockIdx.x >> 2;                 // 4 blocks per batch
    const int c = (blockIdx.x & 3) * 256 + threadIdx.x;

    __shared__ float sc[NREG];
    if (threadIdx.x < NREG) sc[threadIdx.x] = g_scale[threadIdx.x * B + b];
    __syncthreads();

    float o = 0.f;
#pragma unroll
    for (int r = 0; r < NREG; r++)
        o += g_vt[(r * B + b) * C + c] * sc[r];
    out[b * C + c] = o;
}

// ================= launch =================
extern "C" void kernel_launch(void* const* d_in, const int* in_sizes, int n_in,
                              void* d_out, int out_size) {
    const float* x = (const float*)d_in[0];
    float* out = (float*)d_out;
    kZ<<<256, 256>>>();
    kA<<<NBLK, 256>>>(x);
    kB2<<<64, 1024>>>();
    kC1<<<NREG * B, 128>>>();
    kC2<<<64, 256>>>(out);
}